// round 17
// baseline (speedup 1.0000x reference)
#include <cuda_runtime.h>
#include <cuda_fp16.h>
#include <cstdint>

#define N_NODES 100000
#define N_EDGES 1600000
#define F 64
#define SCAN_BLK 512
#define NB ((N_NODES + SCAN_BLK - 1) / SCAN_BLK)   // 196

// Scratch (device globals — zero-initialized at load; no allocation in kernel_launch)
__device__ int    g_cnt[N_NODES];        // zeroed by k_finalize after each use
__device__ int    g_scan[N_NODES];
__device__ int    g_bsum[NB];
__device__ int    g_rowptr[N_NODES + 1];
__device__ int    g_cursor[N_NODES];
__device__ int    g_src[N_EDGES];        // src indices bucketed by dst
__device__ float  g_dinv[N_NODES];
__device__ __half g_xsh[N_NODES * F];    // (x @ W) * dinv[row], fp16

static __device__ __forceinline__ uint32_t s2u(const void* p) {
    return (uint32_t)__cvta_generic_to_shared(p);
}
static __device__ __forceinline__ uint32_t h2_bits(__half2 h) {
    return *reinterpret_cast<uint32_t*>(&h);
}

// count in-degree (real edges only); 4 edges/thread via int4
__global__ void k_count(const int* __restrict__ ei) {
    int t = blockIdx.x * blockDim.x + threadIdx.x;
    if (t < N_EDGES / 4) {
        int4 d4 = ((const int4*)(ei + N_EDGES))[t];
        if ((unsigned)d4.x < N_NODES) atomicAdd(&g_cnt[d4.x], 1);
        if ((unsigned)d4.y < N_NODES) atomicAdd(&g_cnt[d4.y], 1);
        if ((unsigned)d4.z < N_NODES) atomicAdd(&g_cnt[d4.z], 1);
        if ((unsigned)d4.w < N_NODES) atomicAdd(&g_cnt[d4.w], 1);
    }
}

// dinv from completed counts (runs on the GEMM stream, before finalize resets cnt)
__global__ void k_dinv() {
    int i = blockIdx.x * blockDim.x + threadIdx.x;
    if (i < N_NODES) g_dinv[i] = rsqrtf((float)(g_cnt[i] + 1));   // +1 self-loop
}

// per-block inclusive scan of g_cnt — warp-shuffle version (2 barriers)
__global__ void __launch_bounds__(SCAN_BLK) k_scan_block() {
    __shared__ int wsum[16];
    int t = threadIdx.x;
    int lane = t & 31, warp = t >> 5;
    int i = blockIdx.x * SCAN_BLK + t;
    int v = (i < N_NODES) ? g_cnt[i] : 0;
    #pragma unroll
    for (int off = 1; off < 32; off <<= 1) {
        int u = __shfl_up_sync(0xffffffffu, v, off);
        if (lane >= off) v += u;
    }
    if (lane == 31) wsum[warp] = v;
    __syncthreads();
    if (t < 16) {
        int s = wsum[t];
        #pragma unroll
        for (int off = 1; off < 16; off <<= 1) {
            int u = __shfl_up_sync(0x0000ffffu, s, off, 16);
            if (t >= off) s += u;
        }
        wsum[t] = s;
    }
    __syncthreads();
    if (warp > 0) v += wsum[warp - 1];
    if (i < N_NODES) g_scan[i] = v;
    if (t == SCAN_BLK - 1) g_bsum[blockIdx.x] = v;
}

// finalize: per-block cross-block prefix from g_bsum (warp-reduced),
// then rowptr/cursor; resets g_cnt for the next graph replay.
__global__ void __launch_bounds__(SCAN_BLK) k_finalize() {
    __shared__ int base_sh;
    int b = blockIdx.x;
    int t = threadIdx.x;
    if (t < 32) {
        int s = 0;
        for (int j = t; j < b; j += 32) s += g_bsum[j];
        #pragma unroll
        for (int o = 16; o; o >>= 1) s += __shfl_xor_sync(0xffffffffu, s, o);
        if (t == 0) base_sh = s;
    }
    __syncthreads();
    int i = b * SCAN_BLK + t;
    if (i < N_NODES) {
        int incl = g_scan[i] + base_sh;
        int cnt = g_cnt[i];
        g_cnt[i] = 0;                              // restore invariant for replay
        int excl = incl - cnt;
        g_rowptr[i] = excl;
        g_cursor[i] = excl;
        if (i == N_NODES - 1) g_rowptr[N_NODES] = incl;
    }
}

// bucket src indices by dst; 4 edges/thread, int-only stores (no gathers)
__global__ void k_fill(const int* __restrict__ ei) {
    int t = blockIdx.x * blockDim.x + threadIdx.x;
    if (t < N_EDGES / 4) {
        int4 s4 = ((const int4*)ei)[t];
        int4 d4 = ((const int4*)(ei + N_EDGES))[t];
        if ((unsigned)s4.x < N_NODES && (unsigned)d4.x < N_NODES)
            g_src[atomicAdd(&g_cursor[d4.x], 1)] = s4.x;
        if ((unsigned)s4.y < N_NODES && (unsigned)d4.y < N_NODES)
            g_src[atomicAdd(&g_cursor[d4.y], 1)] = s4.y;
        if ((unsigned)s4.z < N_NODES && (unsigned)d4.z < N_NODES)
            g_src[atomicAdd(&g_cursor[d4.z], 1)] = s4.z;
        if ((unsigned)s4.w < N_NODES && (unsigned)d4.w < N_NODES)
            g_src[atomicAdd(&g_cursor[d4.w], 1)] = s4.w;
    }
}

// Tensor-core GEMM: x staged fp32 via cp.async, A fragments by LDS.64 + cvt;
// B (W) fp16 smem + ldmatrix.trans; epilogue folds dinv.
#define GT_ROWS 128
#define XS32 68   // fp32 stage row stride (floats)
#define XPAD 72   // fp16 W row stride (halfs)
__global__ void __launch_bounds__(256) k_gemm(const float* __restrict__ x,
                                              const float* __restrict__ W) {
    __shared__ float  xs32[GT_ROWS * XS32];
    __shared__ __half ws[64 * XPAD];
    int tid = threadIdx.x;
    int row0 = blockIdx.x * GT_ROWS;

    for (int i = tid; i < GT_ROWS * 16; i += 256) {
        int r = i >> 4, c4 = (i & 15) * 4;
        int grow = row0 + r;
        float* dst = &xs32[r * XS32 + c4];
        if (grow < N_NODES) {
            const float* src = x + grow * F + c4;
            asm volatile("cp.async.cg.shared.global [%0], [%1], 16;"
                         :: "r"(s2u(dst)), "l"(src));
        } else {
            *(float4*)dst = make_float4(0.f, 0.f, 0.f, 0.f);
        }
    }
    asm volatile("cp.async.commit_group;");

    const float4* W4 = (const float4*)W;
    for (int i = tid; i < 1024; i += 256) {
        float4 v = W4[i];
        int k = i >> 4, n4 = (i & 15) << 2;
        __half2* p = (__half2*)&ws[k * XPAD + n4];
        p[0] = __floats2half2_rn(v.x, v.y);
        p[1] = __floats2half2_rn(v.z, v.w);
    }
    asm volatile("cp.async.wait_group 0;");
    __syncthreads();

    int warp = tid >> 5, lane = tid & 31;
    int wrow = warp * 16;
    int qr = lane >> 2, qc = (lane & 3) * 2;

    float acc[8][4];
    #pragma unroll
    for (int n = 0; n < 8; n++)
        #pragma unroll
        for (int j = 0; j < 4; j++) acc[n][j] = 0.f;

    uint32_t wbase = s2u(ws);

    #pragma unroll
    for (int ks = 0; ks < 4; ks++) {
        const float* abase = &xs32[(wrow + qr) * XS32 + ks * 16 + qc];
        float2 f0 = *(const float2*)(abase);
        float2 f1 = *(const float2*)(abase + 8 * XS32);
        float2 f2 = *(const float2*)(abase + 8);
        float2 f3 = *(const float2*)(abase + 8 * XS32 + 8);
        uint32_t a0 = h2_bits(__floats2half2_rn(f0.x, f0.y));
        uint32_t a1 = h2_bits(__floats2half2_rn(f1.x, f1.y));
        uint32_t a2 = h2_bits(__floats2half2_rn(f2.x, f2.y));
        uint32_t a3 = h2_bits(__floats2half2_rn(f3.x, f3.y));

        uint32_t brow = wbase + ((uint32_t)(ks * 16 + (lane & 15)) * XPAD) * 2;
        #pragma unroll
        for (int nt = 0; nt < 8; nt++) {
            uint32_t baddr = brow + (uint32_t)(nt * 8) * 2;
            uint32_t b0, b1;
            asm volatile("ldmatrix.sync.aligned.m8n8.x2.trans.shared.b16 {%0,%1}, [%2];"
                         : "=r"(b0), "=r"(b1) : "r"(baddr));
            asm volatile("mma.sync.aligned.m16n8k16.row.col.f32.f16.f16.f32 "
                         "{%0,%1,%2,%3}, {%4,%5,%6,%7}, {%8,%9}, {%0,%1,%2,%3};"
                         : "+f"(acc[nt][0]), "+f"(acc[nt][1]),
                           "+f"(acc[nt][2]), "+f"(acc[nt][3])
                         : "r"(a0), "r"(a1), "r"(a2), "r"(a3), "r"(b0), "r"(b1));
        }
    }

    int mrow = row0 + wrow + qr;
    float d0 = (mrow     < N_NODES) ? g_dinv[mrow]     : 0.f;
    float d1 = (mrow + 8 < N_NODES) ? g_dinv[mrow + 8] : 0.f;
    __half2* o2 = (__half2*)g_xsh;
    int cslot = lane & 3;
    #pragma unroll
    for (int nt = 0; nt < 8; nt++) {
        int h2 = nt * 4 + cslot;
        if (mrow < N_NODES)
            o2[mrow * 32 + h2] = __floats2half2_rn(acc[nt][0] * d0, acc[nt][1] * d0);
        if (mrow + 8 < N_NODES)
            o2[(mrow + 8) * 32 + h2] = __floats2half2_rn(acc[nt][2] * d1, acc[nt][3] * d1);
    }
}

// One warp per dst: 8 lanes/edge, 4 edges/warp-step, unit edge weight.
__global__ void __launch_bounds__(256) k_accum(float* __restrict__ out,
                                               const float* __restrict__ b,
                                               const float* __restrict__ a) {
    int d = (blockIdx.x * blockDim.x + threadIdx.x) >> 5;
    int lane = threadIdx.x & 31;
    if (d >= N_NODES) return;
    int beg = g_rowptr[d];
    int end = g_rowptr[d + 1];
    float dd = g_dinv[d];
    int sl  = lane & 7;
    int grp = lane >> 3;

    const float4* xs4 = (const float4*)g_xsh;
    float2 acc[4] = {{0.f,0.f},{0.f,0.f},{0.f,0.f},{0.f,0.f}};

    if (grp == 0) {                              // self-loop, counted once
        float4 hv = xs4[d * 8 + sl];
        const __half2* h = (const __half2*)&hv;
        #pragma unroll
        for (int j = 0; j < 4; j++) {
            float2 v = __half22float2(h[j]);
            acc[j].x += v.x; acc[j].y += v.y;
        }
    }

    #pragma unroll 2
    for (int i = beg + grp; i < end; i += 4) {
        int s = __ldg(g_src + i);
        float4 hv = __ldg(xs4 + s * 8 + sl);
        const __half2* h = (const __half2*)&hv;
        #pragma unroll
        for (int j = 0; j < 4; j++) {
            float2 v = __half22float2(h[j]);
            acc[j].x += v.x; acc[j].y += v.y;
        }
    }

    #pragma unroll
    for (int j = 0; j < 4; j++) {
        #pragma unroll
        for (int off = 8; off <= 16; off <<= 1) {
            acc[j].x += __shfl_xor_sync(0xffffffffu, acc[j].x, off);
            acc[j].y += __shfl_xor_sync(0xffffffffu, acc[j].y, off);
        }
    }

    if (grp == 0) {
        const float4* b4 = (const float4*)b;
        float slope = a[0];
        float4* o4 = (float4*)(out + d * F);
        #pragma unroll
        for (int half4 = 0; half4 < 2; half4++) {
            float4 bb = b4[sl * 2 + half4];
            float2 a0 = acc[half4 * 2 + 0];
            float2 a1 = acc[half4 * 2 + 1];
            float4 r;
            r.x = a0.x * dd + bb.x;
            r.y = a0.y * dd + bb.y;
            r.z = a1.x * dd + bb.z;
            r.w = a1.y * dd + bb.w;
            r.x = (r.x >= 0.f) ? r.x : slope * r.x;
            r.y = (r.y >= 0.f) ? r.y : slope * r.y;
            r.z = (r.z >= 0.f) ? r.z : slope * r.z;
            r.w = (r.w >= 0.f) ? r.w : slope * r.w;
            o4[sl * 2 + half4] = r;
        }
    }
}

extern "C" void kernel_launch(void* const* d_in, const int* in_sizes, int n_in,
                              void* d_out, int out_size) {
    const float* x  = (const float*)d_in[0];
    const int*   ei = (const int*)d_in[1];   // edge_index [2, E] (int32)
    const float* W  = (const float*)d_in[2];
    const float* b  = (const float*)d_in[3];
    const float* a  = (const float*)d_in[4];
    float* out = (float*)d_out;

    static cudaStream_t s1 = nullptr;
    static cudaEvent_t  eC = nullptr, eD = nullptr, eG = nullptr;
    if (!s1) {
        cudaStreamCreateWithFlags(&s1, cudaStreamNonBlocking);
        cudaEventCreateWithFlags(&eC, cudaEventDisableTiming);
        cudaEventCreateWithFlags(&eD, cudaEventDisableTiming);
        cudaEventCreateWithFlags(&eG, cudaEventDisableTiming);
    }

    // stream0: count
    k_count<<<(N_EDGES / 4 + 255) / 256, 256>>>(ei);
    cudaEventRecord(eC, 0);

    // stream1: dinv (reads g_cnt) -> GEMM
    cudaStreamWaitEvent(s1, eC, 0);
    k_dinv<<<(N_NODES + 255) / 256, 256, 0, s1>>>();
    cudaEventRecord(eD, s1);                 // g_cnt fully read for dinv
    k_gemm<<<(N_NODES + GT_ROWS - 1) / GT_ROWS, 256, 0, s1>>>(x, W);
    cudaEventRecord(eG, s1);

    // stream0: scan -> finalize (waits eD before resetting g_cnt) -> fill
    k_scan_block<<<NB, SCAN_BLK>>>();
    cudaStreamWaitEvent(0, eD, 0);
    k_finalize<<<NB, SCAN_BLK>>>();
    k_fill<<<(N_EDGES / 4 + 255) / 256, 256>>>(ei);

    // join: accum needs fill (stream0) and GEMM (stream1)
    cudaStreamWaitEvent(0, eG, 0);
    k_accum<<<(N_NODES * 32 + 255) / 256, 256>>>(out, b, a);
}